// round 15
// baseline (speedup 1.0000x reference)
#include <cuda_runtime.h>
#include <math.h>

// B = 2048 rows, N = 4095 points/row.
// d_in[0] origin_3D (B,3,1), d_in[1] spherical_3D (B,3,N),
// d_in[2] origin_2D (B,3,1), d_in[3] spherical_2D (B,3,N),
// d_in[4] deformation_field (B,2,N). Output: scalar f32.
//
// diff-of-cumsums == cumsum-of-diffs:
//   carry = origin3 - origin2
//   row = |carry|_1 + sum_j |carry + prefix_j(Delta)|_1 ; row /= (N+1); out = sum rows.
//
// R6 structure (strided coalesced loads -> padded smem transpose -> per-thread
// serial prefix -> one block scan) but split into 2 tiles of 2048 points to
// de-phase-lock the 3 co-resident CTAs (shorter DRAM bursts interleave better).

#define NPTS   4095
#define NB     2048
#define BTH    512
#define TPTS   2048                 // points per tile
#define TITEMS 4                    // 512*4 = 2048
#define TPAD   2112                 // 2048 + 2048/32 pad
#define SMEMB  (3 * TPAD * 4)       // 25344 bytes dynamic smem

__device__ float        g_partials[NB];
__device__ unsigned int g_count = 0;

__global__ void __launch_bounds__(BTH, 3)
mpd_loss_fused(const float* __restrict__ o3,
               const float* __restrict__ s3,
               const float* __restrict__ o2,
               const float* __restrict__ s2,
               const float* __restrict__ df,
               float* __restrict__ out)
{
    extern __shared__ float sm[];
    float* sxm = sm;
    float* sym = sm + TPAD;
    float* szm = sm + 2 * TPAD;

    const int b    = blockIdx.x;
    const int t    = threadIdx.x;
    const int wid  = t >> 5;
    const int lane = t & 31;

    // Single base pointer per tensor; stream offsets fold into LDG immediates.
    const float* s3row = s3 + (size_t)(b * 3) * NPTS;
    const float* s2row = s2 + (size_t)(b * 3) * NPTS;
    const float* dfrow = df + (size_t)(b * 2) * NPTS;

    // Origin carry (issued early to overlap latency).
    float cx = o3[b * 3 + 0] - o2[b * 3 + 0];
    float cy = o3[b * 3 + 1] - o2[b * 3 + 1];
    float cz = o3[b * 3 + 2] - o2[b * 3 + 2];

    __shared__ float wsx[16], wsy[16], wsz[16];

    float acc = 0.f;
    if (t == 0) acc = fabsf(cx) + fabsf(cy) + fabsf(cz);   // j=0 origin term

#pragma unroll
    for (int tile = 0; tile < 2; tile++) {
        const int base = tile * TPTS;

        // ---- Phase 1: strided coalesced loads + trig; deltas -> padded smem ----
#pragma unroll
        for (int i = 0; i < TITEMS; i++) {
            int lj = i * BTH + t;          // tile-local index 0..2047
            int j  = base + lj;
            float ddx = 0.f, ddy = 0.f, ddz = 0.f;
            if (j < NPTS) {
                float r3 = s3row[j];
                float a3 = s3row[j + NPTS]     + dfrow[j];
                float p3 = s3row[j + 2 * NPTS] + dfrow[j + NPTS];
                float r2 = s2row[j];
                float a2 = s2row[j + NPTS];
                float p2 = s2row[j + 2 * NPTS];
                float st3, ct3, sp3, cp3, st2, ct2, sp2, cp2;
                __sincosf(a3, &st3, &ct3);
                __sincosf(p3, &sp3, &cp3);
                __sincosf(a2, &st2, &ct2);
                __sincosf(p2, &sp2, &cp2);
                float rs3 = r3 * st3;
                float rs2 = r2 * st2;
                ddx = rs3 * cp3 - rs2 * cp2;
                ddy = rs3 * sp3 - rs2 * sp2;
                ddz = r3 * ct3 - r2 * ct2;
            }
            int p = lj + (lj >> 5);        // padded: conflict-free (contiguous per warp)
            sxm[p] = ddx; sym[p] = ddy; szm[p] = ddz;
        }
        __syncthreads();

        // ---- Phase 2: per-thread serial totals over 4 contiguous elems ----
        // tile-local element e = 4t+k -> padded idx 4t + (t>>3) + k (conflict-free)
        const int pb = t * TITEMS + (t >> 3);
        float ax = 0.f, ay = 0.f, az = 0.f;
#pragma unroll
        for (int k = 0; k < TITEMS; k++) {
            ax += sxm[pb + k];
            ay += sym[pb + k];
            az += szm[pb + k];
        }

        // ---- 512-wide block scan of thread totals ----
        float ix = ax, iy = ay, iz = az;   // warp-inclusive
#pragma unroll
        for (int d = 1; d < 32; d <<= 1) {
            float ox = __shfl_up_sync(0xffffffffu, ix, d);
            float oy = __shfl_up_sync(0xffffffffu, iy, d);
            float oz = __shfl_up_sync(0xffffffffu, iz, d);
            if (lane >= d) { ix += ox; iy += oy; iz += oz; }
        }
        if (lane == 31) { wsx[wid] = ix; wsy[wid] = iy; wsz[wid] = iz; }
        __syncthreads();
        if (t < 16) {
            float vx = wsx[t], vy = wsy[t], vz = wsz[t];
#pragma unroll
            for (int d = 1; d < 16; d <<= 1) {
                float ox = __shfl_up_sync(0x0000ffffu, vx, d, 16);
                float oy = __shfl_up_sync(0x0000ffffu, vy, d, 16);
                float oz = __shfl_up_sync(0x0000ffffu, vz, d, 16);
                if (t >= d) { vx += ox; vy += oy; vz += oz; }
            }
            wsx[t] = vx; wsy[t] = vy; wsz[t] = vz;
        }
        __syncthreads();

        // exclusive thread offset + running carry
        float rx = cx + (wid ? wsx[wid - 1] : 0.f) + (ix - ax);
        float ry = cy + (wid ? wsy[wid - 1] : 0.f) + (iy - ay);
        float rz = cz + (wid ? wsz[wid - 1] : 0.f) + (iz - az);

        // ---- Phase 3: re-read deltas, running prefix + |.|_1 accumulate ----
#pragma unroll
        for (int k = 0; k < TITEMS; k++) {
            rx += sxm[pb + k];
            ry += sym[pb + k];
            rz += szm[pb + k];
            int j = base + t * TITEMS + k;
            if (j < NPTS)
                acc += fabsf(rx) + fabsf(ry) + fabsf(rz);
        }

        // carry += tile total; barrier also protects ws*/s?m before next tile
        cx += wsx[15];
        cy += wsy[15];
        cz += wsz[15];
        __syncthreads();
    }

    // ---- block reduce acc (wsx safe: barrier above) ----
#pragma unroll
    for (int d = 16; d > 0; d >>= 1)
        acc += __shfl_down_sync(0xffffffffu, acc, d);
    if (lane == 0) wsx[wid] = acc;
    __syncthreads();

    __shared__ bool isLast;
    if (t == 0) {
        float s = 0.f;
#pragma unroll
        for (int k = 0; k < 16; k++) s += wsx[k];
        g_partials[b] = s * (1.0f / (float)(NPTS + 1));
        __threadfence();
        unsigned int c = atomicAdd(&g_count, 1u);
        isLast = (c == NB - 1);
    }
    __syncthreads();

    // ---- fused deterministic final reduction (last block) ----
    if (isLast) {
        float v = g_partials[t] + g_partials[t + 512] +
                  g_partials[t + 1024] + g_partials[t + 1536];
#pragma unroll
        for (int d = 16; d > 0; d >>= 1)
            v += __shfl_down_sync(0xffffffffu, v, d);
        if (lane == 0) wsy[wid] = v;
        __syncthreads();
        if (t == 0) {
            float s = 0.f;
#pragma unroll
            for (int k = 0; k < 16; k++) s += wsy[k];
            out[0] = s;
            g_count = 0;                  // reset for next graph replay
        }
    }
}

extern "C" void kernel_launch(void* const* d_in, const int* in_sizes, int n_in,
                              void* d_out, int out_size)
{
    (void)in_sizes; (void)n_in; (void)out_size;
    const float* o3 = (const float*)d_in[0];
    const float* s3 = (const float*)d_in[1];
    const float* o2 = (const float*)d_in[2];
    const float* s2 = (const float*)d_in[3];
    const float* df = (const float*)d_in[4];
    float* out = (float*)d_out;

    cudaFuncSetAttribute(mpd_loss_fused,
                         cudaFuncAttributeMaxDynamicSharedMemorySize, SMEMB);
    mpd_loss_fused<<<NB, BTH, SMEMB>>>(o3, s3, o2, s2, df, out);
}

// round 16
// speedup vs baseline: 1.1596x; 1.1596x over previous
#include <cuda_runtime.h>
#include <math.h>

// B = 2048 rows, N = 4095 points/row.
// d_in[0] origin_3D (B,3,1), d_in[1] spherical_3D (B,3,N),
// d_in[2] origin_2D (B,3,1), d_in[3] spherical_2D (B,3,N),
// d_in[4] deformation_field (B,2,N). Output: scalar f32.
//
// diff-of-cumsums == cumsum-of-diffs:
//   carry = origin3 - origin2
//   row = |carry|_1 + sum_j |carry + prefix_j(Delta)|_1 ; row /= (N+1); out = sum rows.
//
// R6 structure (best known: strided coalesced loads -> padded smem transpose ->
// per-thread serial prefix -> one 512-wide block scan), with BRANCH-FREE
// phase-1/phase-3 bodies so ptxas can software-pipeline loads across the
// unrolled iterations (only the single j==4095 pad slot is invalid; handle it
// with a clamped index + 0/1 validity multiply instead of a branch).

#define NPTS   4095
#define NB     2048
#define BTH    512
#define ITEMS  8                    // 512*8 = 4096 slots
#define PADDED 4224                 // 4096 + 4096/32 pad
#define SMEMB  (3 * PADDED * 4)     // 50688 bytes dynamic smem

__device__ float        g_partials[NB];
__device__ unsigned int g_count = 0;

__global__ void __launch_bounds__(BTH, 3)
mpd_loss_fused(const float* __restrict__ o3,
               const float* __restrict__ s3,
               const float* __restrict__ o2,
               const float* __restrict__ s2,
               const float* __restrict__ df,
               float* __restrict__ out)
{
    extern __shared__ float sm[];
    float* sxm = sm;
    float* sym = sm + PADDED;
    float* szm = sm + 2 * PADDED;

    const int b    = blockIdx.x;
    const int t    = threadIdx.x;
    const int wid  = t >> 5;
    const int lane = t & 31;

    // Single base pointer per tensor; stream offsets fold into LDG immediates.
    const float* s3row = s3 + (size_t)(b * 3) * NPTS;
    const float* s2row = s2 + (size_t)(b * 3) * NPTS;
    const float* dfrow = df + (size_t)(b * 2) * NPTS;

    // ---- Phase 1: branch-free strided loads + trig; deltas -> padded smem ----
#pragma unroll
    for (int i = 0; i < ITEMS; i++) {
        int j  = i * BTH + t;
        int jc = (j < NPTS) ? j : (NPTS - 1);       // clamp: loads unconditional
        float valid = (j < NPTS) ? 1.0f : 0.0f;

        float r3 = s3row[jc];
        float a3 = s3row[jc + NPTS]     + dfrow[jc];
        float p3 = s3row[jc + 2 * NPTS] + dfrow[jc + NPTS];
        float r2 = s2row[jc];
        float a2 = s2row[jc + NPTS];
        float p2 = s2row[jc + 2 * NPTS];

        float st3, ct3, sp3, cp3, st2, ct2, sp2, cp2;
        __sincosf(a3, &st3, &ct3);
        __sincosf(p3, &sp3, &cp3);
        __sincosf(a2, &st2, &ct2);
        __sincosf(p2, &sp2, &cp2);
        float rs3 = r3 * st3;
        float rs2 = r2 * st2;

        int p = j + (j >> 5);          // pad: conflict-free writes (contiguous per warp)
        sxm[p] = valid * (rs3 * cp3 - rs2 * cp2);
        sym[p] = valid * (rs3 * sp3 - rs2 * sp2);
        szm[p] = valid * (r3 * ct3 - r2 * ct2);
    }

    float cx = o3[b * 3 + 0] - o2[b * 3 + 0];
    float cy = o3[b * 3 + 1] - o2[b * 3 + 1];
    float cz = o3[b * 3 + 2] - o2[b * 3 + 2];

    __syncthreads();

    // ---- Phase 2: per-thread serial totals over 8 contiguous elems ----
    // element e = 8t+k  ->  padded index 8t + (t>>2) + k   (conflict-free reads)
    const int pb = t * ITEMS + (t >> 2);
    float ax = 0.f, ay = 0.f, az = 0.f;
#pragma unroll
    for (int k = 0; k < ITEMS; k++) {
        ax += sxm[pb + k];
        ay += sym[pb + k];
        az += szm[pb + k];
    }

    // ---- single 512-wide block scan of thread totals ----
    __shared__ float wsx[16], wsy[16], wsz[16];
    float ix = ax, iy = ay, iz = az;        // warp-inclusive scan values
#pragma unroll
    for (int d = 1; d < 32; d <<= 1) {
        float ox = __shfl_up_sync(0xffffffffu, ix, d);
        float oy = __shfl_up_sync(0xffffffffu, iy, d);
        float oz = __shfl_up_sync(0xffffffffu, iz, d);
        if (lane >= d) { ix += ox; iy += oy; iz += oz; }
    }
    if (lane == 31) { wsx[wid] = ix; wsy[wid] = iy; wsz[wid] = iz; }
    __syncthreads();
    if (t < 16) {
        float vx = wsx[t], vy = wsy[t], vz = wsz[t];
#pragma unroll
        for (int d = 1; d < 16; d <<= 1) {
            float ox = __shfl_up_sync(0x0000ffffu, vx, d, 16);
            float oy = __shfl_up_sync(0x0000ffffu, vy, d, 16);
            float oz = __shfl_up_sync(0x0000ffffu, vz, d, 16);
            if (t >= d) { vx += ox; vy += oy; vz += oz; }
        }
        wsx[t] = vx; wsy[t] = vy; wsz[t] = vz;
    }
    __syncthreads();

    // exclusive thread offset + origin carry
    float rx = cx + (wid ? wsx[wid - 1] : 0.f) + (ix - ax);
    float ry = cy + (wid ? wsy[wid - 1] : 0.f) + (iy - ay);
    float rz = cz + (wid ? wsz[wid - 1] : 0.f) + (iz - az);

    // ---- Phase 3: branch-free re-read + running prefix + |.|_1 accumulate ----
    float acc = 0.f;
    if (t == 0) acc = fabsf(cx) + fabsf(cy) + fabsf(cz);        // j=0 origin term
#pragma unroll
    for (int k = 0; k < ITEMS; k++) {
        rx += sxm[pb + k];
        ry += sym[pb + k];
        rz += szm[pb + k];
        float valid = (t * ITEMS + k < NPTS) ? 1.0f : 0.0f;
        acc += valid * (fabsf(rx) + fabsf(ry) + fabsf(rz));
    }

    // ---- block reduce acc ----
#pragma unroll
    for (int d = 16; d > 0; d >>= 1)
        acc += __shfl_down_sync(0xffffffffu, acc, d);
    __syncthreads();                        // wsx reads above done before overwrite
    if (lane == 0) wsx[wid] = acc;
    __syncthreads();

    __shared__ bool isLast;
    if (t == 0) {
        float s = 0.f;
#pragma unroll
        for (int k = 0; k < 16; k++) s += wsx[k];
        g_partials[b] = s * (1.0f / (float)(NPTS + 1));
        __threadfence();
        unsigned int c = atomicAdd(&g_count, 1u);
        isLast = (c == NB - 1);
    }
    __syncthreads();

    // ---- fused deterministic final reduction (last block) ----
    if (isLast) {
        float v = g_partials[t] + g_partials[t + 512] +
                  g_partials[t + 1024] + g_partials[t + 1536];
#pragma unroll
        for (int d = 16; d > 0; d >>= 1)
            v += __shfl_down_sync(0xffffffffu, v, d);
        if (lane == 0) wsy[wid] = v;
        __syncthreads();
        if (t == 0) {
            float s = 0.f;
#pragma unroll
            for (int k = 0; k < 16; k++) s += wsy[k];
            out[0] = s;
            g_count = 0;                  // reset for next graph replay
        }
    }
}

extern "C" void kernel_launch(void* const* d_in, const int* in_sizes, int n_in,
                              void* d_out, int out_size)
{
    (void)in_sizes; (void)n_in; (void)out_size;
    const float* o3 = (const float*)d_in[0];
    const float* s3 = (const float*)d_in[1];
    const float* o2 = (const float*)d_in[2];
    const float* s2 = (const float*)d_in[3];
    const float* df = (const float*)d_in[4];
    float* out = (float*)d_out;

    cudaFuncSetAttribute(mpd_loss_fused,
                         cudaFuncAttributeMaxDynamicSharedMemorySize, SMEMB);
    mpd_loss_fused<<<NB, BTH, SMEMB>>>(o3, s3, o2, s2, df, out);
}